// round 4
// baseline (speedup 1.0000x reference)
#include <cuda_runtime.h>

#define B_    2048
#define T_    128
#define I_    130
#define H_    10
#define G3    30            // 3*H
#define ROWS  (B_ * T_)     // 262144 rows per GRU
#define XI_STRIDE 32        // padded row stride for g_xi (128B-aligned rows)
#define XTPB  128           // threads per xi block
#define TILE  128           // rows per xi block (1 row / thread)
#define XS_STRIDE 133       // smem x row stride (5t mod 32 -> conflict-free)

// dynamic smem layout: [ wsh: 1040 ulonglong2 = 16640 B ][ xs: 128*133 floats = 68096 B ]
#define WSH_BYTES (I_ * 8 * 16)
#define XS_BYTES  (TILE * XS_STRIDE * 4)
#define SMEM_BYTES (WSH_BYTES + XS_BYTES)

// Scratch (static device globals: allocation-free per harness rules)
__device__ float g_xi[2][(size_t)ROWS * XI_STRIDE];   // 2 x 32MB, cols 30/31 unused

// ---------------- packed fp32x2 helpers (sm_100+) ----------------
__device__ __forceinline__ unsigned long long pack2f(float lo, float hi) {
    unsigned long long r;
    asm("mov.b64 %0, {%1, %2};" : "=l"(r) : "f"(lo), "f"(hi));
    return r;
}
__device__ __forceinline__ unsigned long long fma2(unsigned long long a,
                                                   unsigned long long b,
                                                   unsigned long long c) {
    unsigned long long d;
    asm("fma.rn.f32x2 %0, %1, %2, %3;" : "=l"(d) : "l"(a), "l"(b), "l"(c));
    return d;
}

__device__ __forceinline__ float sigf(float a) {
    return __fdividef(1.f, 1.f + __expf(-a));
}

// ============================================================================
// Kernel A: xi[row, 0:30] = x[row, 0:130] @ Wih^T + bih   (row = b*T + t)
// One launch covers both GRUs (blockIdx.y). 128 threads x 1 row each, full-k
// tile staged COALESCED (linear float2) into smem, W repacked via smem.
// ============================================================================
__global__ __launch_bounds__(XTPB) void xi_kernel(
    const float* __restrict__ ru,  const float* __restrict__ en,
    const float* __restrict__ ruW, const float* __restrict__ enW,
    const float* __restrict__ rub, const float* __restrict__ enb)
{
    extern __shared__ unsigned char smem_raw[];
    ulonglong2* wsh = (ulonglong2*)smem_raw;              // [k*8+q] f32x2 gate pairs
    float*      xs  = (float*)(smem_raw + WSH_BYTES);     // [row][k], stride 133

    const int gru = blockIdx.y;
    const float* __restrict__ x   = gru ? en  : ru;
    const float* __restrict__ Wih = gru ? enW : ruW;
    const float* __restrict__ bih = gru ? enb : rub;

    const int tid  = threadIdx.x;
    const int row0 = blockIdx.x * TILE;

    // ---- 1) W: coalesced float4 load into xs scratch (3900 floats = 975 f4)
    {
        float4* wraw4 = (float4*)xs;
        const float4* wsrc = (const float4*)Wih;
        for (int i = tid; i < (G3 * I_) / 4; i += XTPB)
            wraw4[i] = wsrc[i];
        // tail: 3900 = 975*4 exactly, no tail
    }
    __syncthreads();

    // ---- 2) repack W from xs scratch into f32x2 gate-pair layout
    {
        const float* wraw = xs;
        for (int e = tid; e < I_ * 8; e += XTPB) {
            int k = e >> 3, q = e & 7, g = q * 4;
            float v0 = (g + 0 < G3) ? wraw[(g + 0) * I_ + k] : 0.f;
            float v1 = (g + 1 < G3) ? wraw[(g + 1) * I_ + k] : 0.f;
            float v2 = (g + 2 < G3) ? wraw[(g + 2) * I_ + k] : 0.f;
            float v3 = (g + 3 < G3) ? wraw[(g + 3) * I_ + k] : 0.f;
            ulonglong2 ee;
            ee.x = pack2f(v0, v1);
            ee.y = pack2f(v2, v3);
            wsh[e] = ee;
        }
    }
    __syncthreads();   // packing must finish before xs is overwritten with x

    // ---- 3) x tile: linear coalesced float2 loads, scatter to xs[r][k]
    {
        const float2* xsrc = (const float2*)(x + (size_t)row0 * I_);
        // 128 rows * 65 float2 = 8320 float2; 65 per thread
#pragma unroll 5
        for (int i = 0; i < (TILE * (I_ / 2)) / XTPB; i++) {
            int idx = tid + i * XTPB;
            int r   = idx / (I_ / 2);
            int k2  = idx - r * (I_ / 2);
            float2 v = xsrc[idx];
            float* d = xs + r * XS_STRIDE + 2 * k2;
            d[0] = v.x;
            d[1] = v.y;
        }
    }

    // ---- accumulators (init with bias)
    unsigned long long acc[15];
#pragma unroll
    for (int jj = 0; jj < 15; jj++)
        acc[jj] = pack2f(bih[2 * jj], bih[2 * jj + 1]);

    __syncthreads();

    // ---- 4) compute: one row per thread, full k sweep from smem
    const float* xb = xs + tid * XS_STRIDE;
#pragma unroll 2
    for (int k = 0; k < I_; k++) {
        float xk = xb[k];
        unsigned long long xp = pack2f(xk, xk);
        const ulonglong2* wp = wsh + k * 8;
#pragma unroll
        for (int q = 0; q < 7; q++) {
            ulonglong2 wv = wp[q];                 // uniform LDS.128 broadcast
            acc[2 * q]     = fma2(wv.x, xp, acc[2 * q]);
            acc[2 * q + 1] = fma2(wv.y, xp, acc[2 * q + 1]);
        }
        ulonglong2 wv = wp[7];
        acc[14] = fma2(wv.x, xp, acc[14]);         // gates 28,29
    }

    // ---- 5) store: 7x STG.128 + 1x STG.64 (row base 128B-aligned)
    {
        float* o = g_xi[gru] + (size_t)(row0 + tid) * XI_STRIDE;
        ulonglong2* v = (ulonglong2*)o;
#pragma unroll
        for (int p = 0; p < 7; p++) {
            ulonglong2 e;
            e.x = acc[2 * p];
            e.y = acc[2 * p + 1];
            v[p] = e;
        }
        ((unsigned long long*)o)[14] = acc[14];    // gates 28,29 at float ofs 28
    }
}

// ============================================================================
// Kernel B: GRU scan + fused head MLP (unchanged from passing R3 version).
// Block = 256 threads = 8 warps = 4 batches x 2 GRUs. Warp lanes 0..29 own
// one gate row of Whh; 13 shuffles per step.
// ============================================================================
__global__ __launch_bounds__(256) void scan_head_kernel(
    const float* __restrict__ ruWhh, const float* __restrict__ rubhh,
    const float* __restrict__ enWhh, const float* __restrict__ enbhh,
    const float* __restrict__ W1, const float* __restrict__ b1,
    const float* __restrict__ W2, const float* __restrict__ b2,
    float* __restrict__ out)
{
    __shared__ float sh[4][2][10];

    const int w    = threadIdx.x >> 5;
    const int lane = threadIdx.x & 31;
    const int pair = w >> 1;           // 0..3 : batch within block
    const int gru  = w & 1;
    const int b    = blockIdx.x * 4 + pair;
    const int lm   = lane % 10;

    const float* Whh = gru ? enWhh : ruWhh;
    const float* bhh = gru ? enbhh : rubhh;

    float wr[10];
    float bb = 0.f;
    if (lane < G3) {
#pragma unroll
        for (int j = 0; j < 10; j++) wr[j] = Whh[lane * 10 + j];
        bb = bhh[lane];
    } else {
#pragma unroll
        for (int j = 0; j < 10; j++) wr[j] = 0.f;
    }

    float h[10];
#pragma unroll
    for (int j = 0; j < 10; j++) h[j] = 0.f;
    float hd = 0.f;                      // distributed copy: hd == h[lane-20] on n-lanes

    const float* __restrict__ xib = g_xi[gru] + (size_t)b * T_ * XI_STRIDE;

    // depth-2 prefetch to cover L2 latency
    float xv  = (lane < G3) ? xib[lane] : 0.f;
    float xv1 = (lane < G3) ? xib[XI_STRIDE + lane] : 0.f;

    const int rsrc = (lane >= 20) ? (lane - 20) : lane;

    for (int t = 0; t < T_; t++) {
        float xv2 = 0.f;
        if (lane < G3 && t + 2 < T_) xv2 = xib[(size_t)(t + 2) * XI_STRIDE + lane];

        float gh = bb;
#pragma unroll
        for (int j = 0; j < 10; j++) gh = fmaf(wr[j], h[j], gh);

        float a   = xv + gh;
        float sig = sigf(a);                               // r (0-9), z (10-19)

        float r    = __shfl_sync(0xFFFFFFFFu, sig, rsrc);  // n-lanes get r_j
        float narg = fmaf(r, gh, xv);
        float s2   = sigf(2.f * narg);
        float tanhv = fmaf(2.f, s2, -1.f);
        float val  = (lane >= 20) ? tanhv : sig;           // lanes 20-29: n

        float zed  = __shfl_sync(0xFFFFFFFFu, val, 10 + lm);  // z_{lm}
        float hnew = val + zed * (hd - val);               // valid on lanes 20-29

        hd = __shfl_sync(0xFFFFFFFFu, hnew, 20 + lm);
#pragma unroll
        for (int j = 0; j < 10; j++)
            h[j] = __shfl_sync(0xFFFFFFFFu, hnew, 20 + j);

        xv  = xv1;
        xv1 = xv2;
    }

    if (lane == 0) {
#pragma unroll
        for (int j = 0; j < 10; j++) sh[pair][gru][j] = h[j];
    }
    __syncthreads();

    // head: warps 0..3, one batch each; lanes 0..19 compute h1[d], warp-reduce
    if (w < 4) {
        float s = 0.f;
        if (lane < 20) {
            float acc = b1[lane];
            const float* w1r = W1 + lane * 20;
#pragma unroll
            for (int j = 0; j < 10; j++) acc = fmaf(w1r[j], sh[w][0][j], acc);
#pragma unroll
            for (int j = 0; j < 10; j++) acc = fmaf(w1r[10 + j], sh[w][1][j], acc);
            s = acc * W2[lane];
        }
#pragma unroll
        for (int off = 16; off; off >>= 1)
            s += __shfl_xor_sync(0xFFFFFFFFu, s, off);
        if (lane == 0) out[blockIdx.x * 4 + w] = s + b2[0];
    }
}

// ============================================================================
extern "C" void kernel_launch(void* const* d_in, const int* in_sizes, int n_in,
                              void* d_out, int out_size)
{
    const float* ru     = (const float*)d_in[0];
    const float* en     = (const float*)d_in[1];
    const float* ru_Wih = (const float*)d_in[2];
    const float* ru_Whh = (const float*)d_in[3];
    const float* ru_bih = (const float*)d_in[4];
    const float* ru_bhh = (const float*)d_in[5];
    const float* en_Wih = (const float*)d_in[6];
    const float* en_Whh = (const float*)d_in[7];
    const float* en_bih = (const float*)d_in[8];
    const float* en_bhh = (const float*)d_in[9];
    const float* W1     = (const float*)d_in[10];
    const float* b1     = (const float*)d_in[11];
    const float* W2     = (const float*)d_in[12];
    const float* b2     = (const float*)d_in[13];
    float* out = (float*)d_out;

    // idempotent, not a stream op: safe under graph capture
    cudaFuncSetAttribute(xi_kernel,
                         cudaFuncAttributeMaxDynamicSharedMemorySize, SMEM_BYTES);

    dim3 gx(ROWS / TILE, 2);   // 2048 x 2
    xi_kernel<<<gx, XTPB, SMEM_BYTES>>>(ru, en, ru_Wih, en_Wih, ru_bih, en_bih);
    scan_head_kernel<<<B_ / 4, 256>>>(ru_Whh, ru_bhh, en_Whh, en_bhh,
                                      W1, b1, W2, b2, out);
}